// round 3
// baseline (speedup 1.0000x reference)
#include <cuda_runtime.h>

// Problem constants (from reference setup_inputs)
#define NB 4            // batch
#define EE 16           // embedding dims
#define HW 320000       // 400*800 pixels per image
#define NV (HW / 4)     // float4 groups per plane = 80000
#define CC 20           // label count
#define CK 19           // kept clusters (label 0 = IGNORE)
#define STR 17          // padded stride for [label][e] shared means
#define EB 4            // dim chunks of 4

// Scratch (no allocations allowed -> __device__ globals)
// g_red: [label][eblock][batch] slots, each slot = 8 float4 = 128B (one L2 line)
// slot[0] holds the float4 partial sum for dims eblock*4 .. eblock*4+3.
__device__ float4 g_red[CC * EB * NB * 8];
__device__ float g_cnt[NB * CC];
__device__ float g_means[NB * CC * EE];
__device__ float g_var[NB * CC];
__device__ float g_distreg[NB];

__device__ __forceinline__ void red4(float4* p, float a, float b, float c, float d) {
    asm volatile("red.global.add.v4.f32 [%0], {%1,%2,%3,%4};"
                 :: "l"(p), "f"(a), "f"(b), "f"(c), "f"(d) : "memory");
}

// ---------------------------------------------------------------------------
// Zero the accumulators (must run every call: graph replays require it)
// ---------------------------------------------------------------------------
__global__ void k_zero() {
    int i = threadIdx.x;
    const float4 z4 = make_float4(0.f, 0.f, 0.f, 0.f);
    for (int j = i; j < CC * EB * NB * 8; j += blockDim.x) g_red[j] = z4;
    for (int j = i; j < NB * CC; j += blockDim.x) { g_cnt[j] = 0.f; g_var[j] = 0.f; }
    if (i < NB) g_distreg[i] = 0.f;
}

// ---------------------------------------------------------------------------
// Pass 1: segment sums via intra-thread 4x4 transpose + vector L2 reductions.
// Each thread owns one float4 group (4 pixels, dim-major). For each chunk of
// 4 dims it loads 4 float4s, regroups per-pixel, and fires one red.v4 per
// pixel into the pixel's (label, chunk, batch) accumulator line.
// Counts use per-warp shared histograms.
// ---------------------------------------------------------------------------
__global__ void __launch_bounds__(256) k_pass1(const float* __restrict__ emb,
                                               const int* __restrict__ tgt) {
    const int n = blockIdx.y;
    __shared__ float scnt[8][32];
    for (int j = threadIdx.x; j < 8 * 32; j += blockDim.x) (&scnt[0][0])[j] = 0.f;
    __syncthreads();
    float* sc = scnt[threadIdx.x >> 5];

    const float4* embn = reinterpret_cast<const float4*>(emb) + (size_t)n * EE * NV;
    const int4*   tgtn = reinterpret_cast<const int4*>(tgt) + (size_t)n * NV;

    for (int v = blockIdx.x * blockDim.x + threadIdx.x; v < NV;
         v += gridDim.x * blockDim.x) {
        int4 L = tgtn[v];
        atomicAdd(&sc[L.x], 1.f);
        atomicAdd(&sc[L.y], 1.f);
        atomicAdd(&sc[L.z], 1.f);
        atomicAdd(&sc[L.w], 1.f);
        float4* bx = &g_red[((L.x * EB) * NB + n) * 8];
        float4* by = &g_red[((L.y * EB) * NB + n) * 8];
        float4* bz = &g_red[((L.z * EB) * NB + n) * 8];
        float4* bw = &g_red[((L.w * EB) * NB + n) * 8];
#pragma unroll
        for (int eb = 0; eb < EB; eb++) {
            float4 a = embn[(size_t)(eb * 4 + 0) * NV + v];
            float4 b = embn[(size_t)(eb * 4 + 1) * NV + v];
            float4 c = embn[(size_t)(eb * 4 + 2) * NV + v];
            float4 d = embn[(size_t)(eb * 4 + 3) * NV + v];
            red4(bx + (size_t)eb * NB * 8, a.x, b.x, c.x, d.x);
            red4(by + (size_t)eb * NB * 8, a.y, b.y, c.y, d.y);
            red4(bz + (size_t)eb * NB * 8, a.z, b.z, c.z, d.z);
            red4(bw + (size_t)eb * NB * 8, a.w, b.w, c.w, d.w);
        }
    }
    __syncthreads();

    if (threadIdx.x < CC) {
        float t = 0.f;
#pragma unroll
        for (int w = 0; w < 8; w++) t += scnt[w][threadIdx.x];
        atomicAdd(&g_cnt[n * CC + threadIdx.x], t);
    }
}

// ---------------------------------------------------------------------------
// Means + distance (push) term + regularizer. One block per batch.
// ---------------------------------------------------------------------------
__global__ void k_means() {
    const int n = blockIdx.x;
    __shared__ float m[CC * STR];
    __shared__ float cnt[CC];
    __shared__ float acc[2];
    const int tid = threadIdx.x;

    if (tid < 2) acc[tid] = 0.f;
    if (tid < CC) cnt[tid] = g_cnt[n * CC + tid];
    __syncthreads();

    const float* redf = reinterpret_cast<const float*>(g_red);
    for (int j = tid; j < CC * EE; j += blockDim.x) {
        int lab = j / EE, e = j % EE;
        int eb = e >> 2, r = e & 3;
        float sum = redf[(((lab * EB + eb) * NB + n) * 8) * 4 + r];
        float mv = sum / cnt[lab];
        m[lab * STR + e] = mv;
        g_means[n * CC * EE + j] = mv;
    }
    __syncthreads();

    // push term over kept clusters (labels 1..19)
    float part = 0.f;
    for (int pr = tid; pr < CK * CK; pr += blockDim.x) {
        int i = pr / CK + 1, j2 = pr % CK + 1;
        if (i != j2) {
            float d2 = 0.f;
#pragma unroll
            for (int e = 0; e < EE; e++) {
                float df = m[i * STR + e] - m[j2 * STR + e];
                d2 += df * df;
            }
            float dm = (d2 > 0.f) ? sqrtf(d2) : 0.f;
            float h = fmaxf(3.0f - dm, 0.f);   // 2*DELTA_DIST = 3
            part += h * h;
        }
    }
    // regularizer: sum of ||mean_k||
    float reg = 0.f;
    for (int c = tid + 1; c < CC; c += blockDim.x) {
        float d2 = 0.f;
#pragma unroll
        for (int e = 0; e < EE; e++) {
            float mv = m[c * STR + e];
            d2 += mv * mv;
        }
        reg += (d2 > 0.f) ? sqrtf(d2) : 0.f;
    }
    atomicAdd(&acc[0], part);
    atomicAdd(&acc[1], reg);
    __syncthreads();
    if (tid == 0)
        g_distreg[n] = acc[0] / (float)(CK * (CK - 1)) + 0.001f * acc[1] / (float)CK;
}

// ---------------------------------------------------------------------------
// Pass 2: variance (pull) term. Per pixel: ||x - mean[lab]||, hinge^2, segment sum.
// ---------------------------------------------------------------------------
__global__ void __launch_bounds__(256) k_pass2(const float* __restrict__ emb,
                                               const int* __restrict__ tgt) {
    const int n = blockIdx.y;
    __shared__ float m[CC * STR];
    __shared__ float sv[CC];
    const int tid = threadIdx.x;

    for (int j = tid; j < CC * EE; j += blockDim.x) {
        int lab = j / EE, e = j % EE;
        m[lab * STR + e] = g_means[n * CC * EE + j];
    }
    if (tid < CC) sv[tid] = 0.f;
    __syncthreads();

    const float4* embn = reinterpret_cast<const float4*>(emb) + (size_t)n * EE * NV;
    const int4*   tgtn = reinterpret_cast<const int4*>(tgt) + (size_t)n * NV;

    for (int v = blockIdx.x * blockDim.x + tid; v < NV;
         v += gridDim.x * blockDim.x) {
        int4 L = tgtn[v];
        int bx = L.x * STR, by = L.y * STR, bz = L.z * STR, bw = L.w * STR;
        float d0 = 0.f, d1 = 0.f, d2 = 0.f, d3 = 0.f;
#pragma unroll
        for (int e = 0; e < EE; e++) {
            float4 x = embn[(size_t)e * NV + v];
            float t0 = x.x - m[bx + e]; d0 = fmaf(t0, t0, d0);
            float t1 = x.y - m[by + e]; d1 = fmaf(t1, t1, d1);
            float t2 = x.z - m[bz + e]; d2 = fmaf(t2, t2, d2);
            float t3 = x.w - m[bw + e]; d3 = fmaf(t3, t3, d3);
        }
        if (L.x != 0) { float d = sqrtf(d0); float h = fmaxf(d - 0.5f, 0.f); atomicAdd(&sv[L.x], h * h); }
        if (L.y != 0) { float d = sqrtf(d1); float h = fmaxf(d - 0.5f, 0.f); atomicAdd(&sv[L.y], h * h); }
        if (L.z != 0) { float d = sqrtf(d2); float h = fmaxf(d - 0.5f, 0.f); atomicAdd(&sv[L.z], h * h); }
        if (L.w != 0) { float d = sqrtf(d3); float h = fmaxf(d - 0.5f, 0.f); atomicAdd(&sv[L.w], h * h); }
    }
    __syncthreads();
    if (tid < CC) atomicAdd(&g_var[n * CC + tid], sv[tid]);
}

// ---------------------------------------------------------------------------
// Finalize: combine variance, distance, reg terms; mean over batches.
// ---------------------------------------------------------------------------
__global__ void k_final(float* __restrict__ out) {
    __shared__ float s[NB];
    const int tid = threadIdx.x;
    if (tid < NB) s[tid] = 0.f;
    __syncthreads();
    if (tid < NB * CK) {
        int n = tid / CK, c = tid % CK + 1;
        atomicAdd(&s[n], g_var[n * CC + c] / g_cnt[n * CC + c]);
    }
    __syncthreads();
    if (tid == 0) {
        float tot = 0.f;
        for (int n = 0; n < NB; n++)
            tot += s[n] / (float)CK + g_distreg[n];
        out[0] = tot / (float)NB;
    }
}

// ---------------------------------------------------------------------------
extern "C" void kernel_launch(void* const* d_in, const int* in_sizes, int n_in,
                              void* d_out, int out_size) {
    const float* emb = (const float*)d_in[0];
    const int*   tgt = (const int*)d_in[1];
    float*       out = (float*)d_out;

    k_zero<<<1, 256>>>();
    k_pass1<<<dim3(296, NB), 256>>>(emb, tgt);
    k_means<<<NB, 128>>>();
    k_pass2<<<dim3(296, NB), 256>>>(emb, tgt);
    k_final<<<1, 128>>>(out);
}

// round 5
// speedup vs baseline: 2.0746x; 2.0746x over previous
#include <cuda_runtime.h>

// Problem constants (from reference setup_inputs)
#define NB 4            // batch
#define EE 16           // embedding dims
#define HW 320000       // 400*800 pixels per image
#define NV (HW / 4)     // float4 groups per plane = 80000
#define CC 20           // label count
#define CK 19           // kept clusters (label 0 = IGNORE)
#define STR 17          // padded stride for [label][e]; slot 16 = count
#define GRIDX 313       // 313*256 = 80128 >= NV : exact cover, one item/thread

// Scratch (no allocations allowed -> __device__ globals)
__device__ float g_sums[NB * CC * EE];
__device__ float g_cnt[NB * CC];
__device__ float g_means[NB * CC * EE];
__device__ float g_var[NB * CC];
__device__ float g_distreg[NB];

// ---------------------------------------------------------------------------
// Zero the accumulators (must run every call: graph replays require it)
// ---------------------------------------------------------------------------
__global__ void k_zero() {
    int i = threadIdx.x;
    for (int j = i; j < NB * CC * EE; j += blockDim.x) g_sums[j] = 0.f;
    for (int j = i; j < NB * CC; j += blockDim.x) { g_cnt[j] = 0.f; g_var[j] = 0.f; }
    if (i < NB) g_distreg[i] = 0.f;
}

// ---------------------------------------------------------------------------
// Pass 1: segment sums + counts per (batch, label, dim).
// 8 per-warp private shared replicas of [CC][STR] (stride 17 => for fixed e,
// the 20 labels land on 20 distinct banks). Slot e==16 carries the count.
// Exact-cover grid: every thread handles exactly one float4 group.
// ---------------------------------------------------------------------------
__global__ void __launch_bounds__(256) k_pass1(const float* __restrict__ emb,
                                               const int* __restrict__ tgt) {
    const int n = blockIdx.y;
    __shared__ float s[8][CC * STR];
    for (int j = threadIdx.x; j < 8 * CC * STR; j += blockDim.x)
        (&s[0][0])[j] = 0.f;
    __syncthreads();

    float* sr = s[threadIdx.x >> 5];
    const int v = blockIdx.x * blockDim.x + threadIdx.x;

    if (v < NV) {
        const float4* embn = reinterpret_cast<const float4*>(emb) + (size_t)n * EE * NV;
        const int4*   tgtn = reinterpret_cast<const int4*>(tgt) + (size_t)n * NV;

        int4 L = tgtn[v];
        int bx = L.x * STR, by = L.y * STR, bz = L.z * STR, bw = L.w * STR;
        atomicAdd(&sr[bx + 16], 1.f);
        atomicAdd(&sr[by + 16], 1.f);
        atomicAdd(&sr[bz + 16], 1.f);
        atomicAdd(&sr[bw + 16], 1.f);
#pragma unroll
        for (int e = 0; e < EE; e++) {
            float4 x = embn[(size_t)e * NV + v];
            atomicAdd(&sr[bx + e], x.x);
            atomicAdd(&sr[by + e], x.y);
            atomicAdd(&sr[bz + e], x.z);
            atomicAdd(&sr[bw + e], x.w);
        }
    }
    __syncthreads();

    for (int j = threadIdx.x; j < CC * STR; j += blockDim.x) {
        float vsum = s[0][j] + s[1][j] + s[2][j] + s[3][j]
                   + s[4][j] + s[5][j] + s[6][j] + s[7][j];
        int lab = j / STR, e = j % STR;
        if (e < EE)
            atomicAdd(&g_sums[(n * CC + lab) * EE + e], vsum);
        else
            atomicAdd(&g_cnt[n * CC + lab], vsum);
    }
}

// ---------------------------------------------------------------------------
// Means + distance (push) term + regularizer. One block per batch.
// ---------------------------------------------------------------------------
__global__ void k_means() {
    const int n = blockIdx.x;
    __shared__ float m[CC * STR];
    __shared__ float cnt[CC];
    __shared__ float acc[2];
    const int tid = threadIdx.x;

    if (tid < 2) acc[tid] = 0.f;
    if (tid < CC) cnt[tid] = g_cnt[n * CC + tid];
    __syncthreads();

    for (int j = tid; j < CC * EE; j += blockDim.x) {
        int lab = j / EE, e = j % EE;
        float mv = g_sums[n * CC * EE + j] / cnt[lab];
        m[lab * STR + e] = mv;
        g_means[n * CC * EE + j] = mv;
    }
    __syncthreads();

    // push term over kept clusters (labels 1..19)
    float part = 0.f;
    for (int pr = tid; pr < CK * CK; pr += blockDim.x) {
        int i = pr / CK + 1, j2 = pr % CK + 1;
        if (i != j2) {
            float d2 = 0.f;
#pragma unroll
            for (int e = 0; e < EE; e++) {
                float df = m[i * STR + e] - m[j2 * STR + e];
                d2 += df * df;
            }
            float dm = (d2 > 0.f) ? sqrtf(d2) : 0.f;
            float h = fmaxf(3.0f - dm, 0.f);   // 2*DELTA_DIST = 3
            part += h * h;
        }
    }
    // regularizer: sum of ||mean_k||
    float reg = 0.f;
    for (int c = tid + 1; c < CC; c += blockDim.x) {
        float d2 = 0.f;
#pragma unroll
        for (int e = 0; e < EE; e++) {
            float mv = m[c * STR + e];
            d2 += mv * mv;
        }
        reg += (d2 > 0.f) ? sqrtf(d2) : 0.f;
    }
    atomicAdd(&acc[0], part);
    atomicAdd(&acc[1], reg);
    __syncthreads();
    if (tid == 0)
        g_distreg[n] = acc[0] / (float)(CK * (CK - 1)) + 0.001f * acc[1] / (float)CK;
}

// ---------------------------------------------------------------------------
// Pass 2: variance (pull) term. Per pixel: ||x - mean[lab]||, hinge^2,
// segment sum. Exact-cover grid: one float4 group per thread, no loop.
// ---------------------------------------------------------------------------
__global__ void __launch_bounds__(256) k_pass2(const float* __restrict__ emb,
                                               const int* __restrict__ tgt) {
    const int n = blockIdx.y;
    __shared__ float m[CC * STR];
    __shared__ float sv[CC];
    const int tid = threadIdx.x;

    for (int j = tid; j < CC * EE; j += blockDim.x) {
        int lab = j / EE, e = j % EE;
        m[lab * STR + e] = g_means[n * CC * EE + j];
    }
    if (tid < CC) sv[tid] = 0.f;
    __syncthreads();

    const int v = blockIdx.x * blockDim.x + tid;
    if (v < NV) {
        const float4* embn = reinterpret_cast<const float4*>(emb) + (size_t)n * EE * NV;
        const int4*   tgtn = reinterpret_cast<const int4*>(tgt) + (size_t)n * NV;

        int4 L = tgtn[v];
        int bx = L.x * STR, by = L.y * STR, bz = L.z * STR, bw = L.w * STR;
        float d0 = 0.f, d1 = 0.f, d2 = 0.f, d3 = 0.f;
#pragma unroll
        for (int e = 0; e < EE; e++) {
            float4 x = embn[(size_t)e * NV + v];
            float t0 = x.x - m[bx + e]; d0 = fmaf(t0, t0, d0);
            float t1 = x.y - m[by + e]; d1 = fmaf(t1, t1, d1);
            float t2 = x.z - m[bz + e]; d2 = fmaf(t2, t2, d2);
            float t3 = x.w - m[bw + e]; d3 = fmaf(t3, t3, d3);
        }
        if (L.x != 0) { float d = sqrtf(d0); float h = fmaxf(d - 0.5f, 0.f); atomicAdd(&sv[L.x], h * h); }
        if (L.y != 0) { float d = sqrtf(d1); float h = fmaxf(d - 0.5f, 0.f); atomicAdd(&sv[L.y], h * h); }
        if (L.z != 0) { float d = sqrtf(d2); float h = fmaxf(d - 0.5f, 0.f); atomicAdd(&sv[L.z], h * h); }
        if (L.w != 0) { float d = sqrtf(d3); float h = fmaxf(d - 0.5f, 0.f); atomicAdd(&sv[L.w], h * h); }
    }
    __syncthreads();
    if (tid < CC) atomicAdd(&g_var[n * CC + tid], sv[tid]);
}

// ---------------------------------------------------------------------------
// Finalize: combine variance, distance, reg terms; mean over batches.
// ---------------------------------------------------------------------------
__global__ void k_final(float* __restrict__ out) {
    __shared__ float s[NB];
    const int tid = threadIdx.x;
    if (tid < NB) s[tid] = 0.f;
    __syncthreads();
    if (tid < NB * CK) {
        int n = tid / CK, c = tid % CK + 1;
        atomicAdd(&s[n], g_var[n * CC + c] / g_cnt[n * CC + c]);
    }
    __syncthreads();
    if (tid == 0) {
        float tot = 0.f;
        for (int n = 0; n < NB; n++)
            tot += s[n] / (float)CK + g_distreg[n];
        out[0] = tot / (float)NB;
    }
}

// ---------------------------------------------------------------------------
extern "C" void kernel_launch(void* const* d_in, const int* in_sizes, int n_in,
                              void* d_out, int out_size) {
    const float* emb = (const float*)d_in[0];
    const int*   tgt = (const int*)d_in[1];
    float*       out = (float*)d_out;

    k_zero<<<1, 256>>>();
    k_pass1<<<dim3(GRIDX, NB), 256>>>(emb, tgt);
    k_means<<<NB, 128>>>();
    k_pass2<<<dim3(GRIDX, NB), 256>>>(emb, tgt);
    k_final<<<1, 128>>>(out);
}

// round 9
// speedup vs baseline: 2.3521x; 1.1338x over previous
#include <cuda_runtime.h>

// Problem constants (from reference setup_inputs)
#define NB 4            // batch
#define EE 16           // embedding dims
#define HW 320000       // 400*800 pixels per image
#define NV (HW / 4)     // float4 groups per plane = 80000
#define NV2 (NV / 2)    // 40000: each thread handles groups v and v+NV2
#define CC 20           // label count
#define CK 19           // kept clusters (label 0 = IGNORE)
#define STR 17          // padded stride for [label][e] shared means
#define EB 4            // dim chunks of 4
#define RR 128          // L2 accumulator replicas
#define GRIDX 157       // 157*256 = 40192 >= NV2 : exact cover, 2 groups/thread

// g_red: [label][eblock][batch][replica] lines; each line = 8 float4 = 128 B
// (one L2 line). Only float4[0] of each line is used as the accumulator.
#define REDLINES (CC * EB * NB * RR)     // 40960 lines
__device__ float4 g_red[REDLINES * 8];   // 5.24 MB, stays in L2
__device__ float g_cnt[NB * CC];
__device__ float g_means[NB * CC * EE];
__device__ float g_var[NB * CC];
__device__ float g_distreg[NB];

__device__ __forceinline__ void red4(float4* p, float a, float b, float c, float d) {
    asm volatile("red.global.add.v4.f32 [%0], {%1,%2,%3,%4};"
                 :: "l"(p), "f"(a), "f"(b), "f"(c), "f"(d) : "memory");
}

// ---------------------------------------------------------------------------
// Zero the accumulators (graph replays accumulate via RED -> must re-zero)
// ---------------------------------------------------------------------------
__global__ void __launch_bounds__(256) k_zero() {
    const float4 z4 = make_float4(0.f, 0.f, 0.f, 0.f);
    int i = blockIdx.x * blockDim.x + threadIdx.x;
    for (int j = i; j < REDLINES * 8; j += gridDim.x * blockDim.x) g_red[j] = z4;
    if (blockIdx.x == 0) {
        for (int j = threadIdx.x; j < NB * CC; j += blockDim.x) {
            g_cnt[j] = 0.f; g_var[j] = 0.f;
        }
        if (threadIdx.x < NB) g_distreg[threadIdx.x] = 0.f;
    }
}

// ---------------------------------------------------------------------------
// Pass 1: segment sums via intra-thread 4x4 transpose + replicated vector L2
// reductions. Each thread handles 2 float4 groups (8 pixels). For each chunk
// of 4 dims it regroups per-pixel in registers and fires one red.v4 into the
// pixel's (label, chunk, batch, replica) line. 128 replicas kill per-address
// serialization at the LTS. Counts use per-warp shared histograms.
// ---------------------------------------------------------------------------
__device__ __forceinline__ void p1_group(const float4* __restrict__ embn,
                                         const int4* __restrict__ tgtn,
                                         int v, int off0, float* sc) {
    int4 L = tgtn[v];
    atomicAdd(&sc[L.x], 1.f);
    atomicAdd(&sc[L.y], 1.f);
    atomicAdd(&sc[L.z], 1.f);
    atomicAdd(&sc[L.w], 1.f);
    // line index = lab*(EB*NB*RR) + eb*(NB*RR) + n*RR + rep ; float4 idx = line*8
    int bx = (L.x * (EB * NB * RR) + off0) * 8;
    int by = (L.y * (EB * NB * RR) + off0) * 8;
    int bz = (L.z * (EB * NB * RR) + off0) * 8;
    int bw = (L.w * (EB * NB * RR) + off0) * 8;
#pragma unroll
    for (int eb = 0; eb < EB; eb++) {
        float4 a = embn[(size_t)(eb * 4 + 0) * NV + v];
        float4 b = embn[(size_t)(eb * 4 + 1) * NV + v];
        float4 c = embn[(size_t)(eb * 4 + 2) * NV + v];
        float4 d = embn[(size_t)(eb * 4 + 3) * NV + v];
        const int ebo = eb * (NB * RR) * 8;
        red4(&g_red[bx + ebo], a.x, b.x, c.x, d.x);
        red4(&g_red[by + ebo], a.y, b.y, c.y, d.y);
        red4(&g_red[bz + ebo], a.z, b.z, c.z, d.z);
        red4(&g_red[bw + ebo], a.w, b.w, c.w, d.w);
    }
}

__global__ void __launch_bounds__(256) k_pass1(const float* __restrict__ emb,
                                               const int* __restrict__ tgt) {
    const int n = blockIdx.y;
    __shared__ float scnt[8][32];
    for (int j = threadIdx.x; j < 8 * 32; j += blockDim.x) (&scnt[0][0])[j] = 0.f;
    __syncthreads();
    float* sc = scnt[threadIdx.x >> 5];

    const int idx = blockIdx.x * blockDim.x + threadIdx.x;
    const int rep = (blockIdx.x * 8 + (threadIdx.x >> 5) + n * 37) & (RR - 1);
    const int off0 = n * RR + rep;

    if (idx < NV2) {
        const float4* embn = reinterpret_cast<const float4*>(emb) + (size_t)n * EE * NV;
        const int4*   tgtn = reinterpret_cast<const int4*>(tgt) + (size_t)n * NV;
        p1_group(embn, tgtn, idx, off0, sc);
        p1_group(embn, tgtn, idx + NV2, off0, sc);
    }
    __syncthreads();

    if (threadIdx.x < CC) {
        float t = 0.f;
#pragma unroll
        for (int w = 0; w < 8; w++) t += scnt[w][threadIdx.x];
        atomicAdd(&g_cnt[n * CC + threadIdx.x], t);
    }
}

// ---------------------------------------------------------------------------
// Means (replica reduction) + distance (push) term + regularizer.
// One block (256 threads) per batch. Phase A: each warp reduces the 128
// replicas of a (label, dim-chunk) accumulator via strided loads + butterfly.
// ---------------------------------------------------------------------------
__global__ void __launch_bounds__(256) k_means() {
    const int n = blockIdx.x;
    __shared__ float m[CC * STR];
    __shared__ float cnt[CC];
    __shared__ float acc[2];
    const int tid = threadIdx.x;
    const int wid = tid >> 5, lane = tid & 31;

    if (tid < 2) acc[tid] = 0.f;
    if (tid < CC) cnt[tid] = g_cnt[n * CC + tid];
    __syncthreads();

    // Phase A: 80 (lab, eb) pairs; warp w handles pairs w, w+8, ...
    for (int p = wid; p < CC * EB; p += 8) {
        int lab = p / EB, eb = p % EB;
        int base = (lab * (EB * NB * RR) + eb * (NB * RR) + n * RR) * 8;
        float4 a = make_float4(0.f, 0.f, 0.f, 0.f);
#pragma unroll
        for (int r = 0; r < RR / 32; r++) {
            float4 t = g_red[base + (lane + r * 32) * 8];
            a.x += t.x; a.y += t.y; a.z += t.z; a.w += t.w;
        }
#pragma unroll
        for (int s = 16; s > 0; s >>= 1) {
            a.x += __shfl_xor_sync(0xffffffffu, a.x, s);
            a.y += __shfl_xor_sync(0xffffffffu, a.y, s);
            a.z += __shfl_xor_sync(0xffffffffu, a.z, s);
            a.w += __shfl_xor_sync(0xffffffffu, a.w, s);
        }
        if (lane == 0) {
            float ic = 1.f / cnt[lab];
            int e0 = eb * 4;
            m[lab * STR + e0 + 0] = a.x * ic;
            m[lab * STR + e0 + 1] = a.y * ic;
            m[lab * STR + e0 + 2] = a.z * ic;
            m[lab * STR + e0 + 3] = a.w * ic;
            g_means[n * CC * EE + lab * EE + e0 + 0] = a.x * ic;
            g_means[n * CC * EE + lab * EE + e0 + 1] = a.y * ic;
            g_means[n * CC * EE + lab * EE + e0 + 2] = a.z * ic;
            g_means[n * CC * EE + lab * EE + e0 + 3] = a.w * ic;
        }
    }
    __syncthreads();

    // push term over kept clusters (labels 1..19)
    float part = 0.f;
    for (int pr = tid; pr < CK * CK; pr += blockDim.x) {
        int i = pr / CK + 1, j2 = pr % CK + 1;
        if (i != j2) {
            float d2 = 0.f;
#pragma unroll
            for (int e = 0; e < EE; e++) {
                float df = m[i * STR + e] - m[j2 * STR + e];
                d2 += df * df;
            }
            float dm = (d2 > 0.f) ? sqrtf(d2) : 0.f;
            float h = fmaxf(3.0f - dm, 0.f);   // 2*DELTA_DIST = 3
            part += h * h;
        }
    }
    // regularizer: sum of ||mean_k||
    float reg = 0.f;
    for (int c = tid + 1; c < CC; c += blockDim.x) {
        float d2 = 0.f;
#pragma unroll
        for (int e = 0; e < EE; e++) {
            float mv = m[c * STR + e];
            d2 += mv * mv;
        }
        reg += (d2 > 0.f) ? sqrtf(d2) : 0.f;
    }
    atomicAdd(&acc[0], part);
    atomicAdd(&acc[1], reg);
    __syncthreads();
    if (tid == 0)
        g_distreg[n] = acc[0] / (float)(CK * (CK - 1)) + 0.001f * acc[1] / (float)CK;
}

// ---------------------------------------------------------------------------
// Pass 2: variance (pull) term. Per pixel: ||x - mean[lab]||, hinge^2,
// segment sum. 2 float4 groups per thread, single wave.
// ---------------------------------------------------------------------------
__device__ __forceinline__ void p2_group(const float4* __restrict__ embn,
                                         const int4* __restrict__ tgtn,
                                         int v, const float* m, float* sv) {
    int4 L = tgtn[v];
    int bx = L.x * STR, by = L.y * STR, bz = L.z * STR, bw = L.w * STR;
    float d0 = 0.f, d1 = 0.f, d2 = 0.f, d3 = 0.f;
#pragma unroll
    for (int e = 0; e < EE; e++) {
        float4 x = embn[(size_t)e * NV + v];
        float t0 = x.x - m[bx + e]; d0 = fmaf(t0, t0, d0);
        float t1 = x.y - m[by + e]; d1 = fmaf(t1, t1, d1);
        float t2 = x.z - m[bz + e]; d2 = fmaf(t2, t2, d2);
        float t3 = x.w - m[bw + e]; d3 = fmaf(t3, t3, d3);
    }
    if (L.x != 0) { float d = sqrtf(d0); float h = fmaxf(d - 0.5f, 0.f); atomicAdd(&sv[L.x], h * h); }
    if (L.y != 0) { float d = sqrtf(d1); float h = fmaxf(d - 0.5f, 0.f); atomicAdd(&sv[L.y], h * h); }
    if (L.z != 0) { float d = sqrtf(d2); float h = fmaxf(d - 0.5f, 0.f); atomicAdd(&sv[L.z], h * h); }
    if (L.w != 0) { float d = sqrtf(d3); float h = fmaxf(d - 0.5f, 0.f); atomicAdd(&sv[L.w], h * h); }
}

__global__ void __launch_bounds__(256) k_pass2(const float* __restrict__ emb,
                                               const int* __restrict__ tgt) {
    const int n = blockIdx.y;
    __shared__ float m[CC * STR];
    __shared__ float sv[CC];
    const int tid = threadIdx.x;

    for (int j = tid; j < CC * EE; j += blockDim.x) {
        int lab = j / EE, e = j % EE;
        m[lab * STR + e] = g_means[n * CC * EE + j];
    }
    if (tid < CC) sv[tid] = 0.f;
    __syncthreads();

    const int idx = blockIdx.x * blockDim.x + tid;
    if (idx < NV2) {
        const float4* embn = reinterpret_cast<const float4*>(emb) + (size_t)n * EE * NV;
        const int4*   tgtn = reinterpret_cast<const int4*>(tgt) + (size_t)n * NV;
        p2_group(embn, tgtn, idx, m, sv);
        p2_group(embn, tgtn, idx + NV2, m, sv);
    }
    __syncthreads();
    if (tid < CC) atomicAdd(&g_var[n * CC + tid], sv[tid]);
}

// ---------------------------------------------------------------------------
// Finalize: combine variance, distance, reg terms; mean over batches.
// ---------------------------------------------------------------------------
__global__ void k_final(float* __restrict__ out) {
    __shared__ float s[NB];
    const int tid = threadIdx.x;
    if (tid < NB) s[tid] = 0.f;
    __syncthreads();
    if (tid < NB * CK) {
        int n = tid / CK, c = tid % CK + 1;
        atomicAdd(&s[n], g_var[n * CC + c] / g_cnt[n * CC + c]);
    }
    __syncthreads();
    if (tid == 0) {
        float tot = 0.f;
        for (int n = 0; n < NB; n++)
            tot += s[n] / (float)CK + g_distreg[n];
        out[0] = tot / (float)NB;
    }
}

// ---------------------------------------------------------------------------
extern "C" void kernel_launch(void* const* d_in, const int* in_sizes, int n_in,
                              void* d_out, int out_size) {
    const float* emb = (const float*)d_in[0];
    const int*   tgt = (const int*)d_in[1];
    float*       out = (float*)d_out;

    k_zero<<<512, 256>>>();
    k_pass1<<<dim3(GRIDX, NB), 256>>>(emb, tgt);
    k_means<<<NB, 256>>>();
    k_pass2<<<dim3(GRIDX, NB), 256>>>(emb, tgt);
    k_final<<<1, 128>>>(out);
}